// round 17
// baseline (speedup 1.0000x reference)
#include <cuda_runtime.h>
#include <cuda_fp16.h>
#include <stdint.h>
#include <math.h>

#define EMB   2048
#define NH    16
#define DH    128
#define BSZ   4
#define TLEN  2048
#define MROWS (BSZ*TLEN)   // 8192
#define NQKV  2304         // 2048 (Q heads) + 128 (K) + 128 (V)
#define GK    2048         // GEMM K depth

// ---------------- scratch (static device globals; no allocations) ----------
__device__ __half g_Xh[MROWS*GK];                     // x -> fp16
__device__ __half g_Ch[MROWS*NQKV], g_Cl[MROWS*NQKV]; // split QKV out
__device__ __half g_Ah[MROWS*EMB];                    // attn out -> fp16
__device__ __half g_Wth[NQKV*GK];                     // [Wq|Wk|Wv]^T [N,K] hi
__device__ __half g_Woth[EMB*GK];                     // Wo^T [N,K] hi

// ==================== helpers ==============================================
__device__ __forceinline__ uint32_t smem_u32(const void* p) {
    uint32_t a;
    asm("{ .reg .u64 t; cvta.to.shared.u64 t, %1; cvt.u32.u64 %0, t; }"
        : "=r"(a) : "l"(p));
    return a;
}
__device__ __forceinline__ void cp_async16(uint32_t dst, const void* src) {
    asm volatile("cp.async.cg.shared.global [%0], [%1], 16;\n"
                 :: "r"(dst), "l"(src));
}
#define CP_COMMIT()  asm volatile("cp.async.commit_group;\n" ::: "memory")
#define CP_WAIT(n)   asm volatile("cp.async.wait_group %0;\n" :: "n"(n) : "memory")

__device__ __forceinline__ void ldm_x4(uint32_t& r0, uint32_t& r1,
                                       uint32_t& r2, uint32_t& r3, uint32_t a) {
    asm volatile("ldmatrix.sync.aligned.m8n8.x4.shared.b16 {%0,%1,%2,%3}, [%4];"
                 : "=r"(r0), "=r"(r1), "=r"(r2), "=r"(r3) : "r"(a));
}
__device__ __forceinline__ void ldm_x4t(uint32_t& r0, uint32_t& r1,
                                        uint32_t& r2, uint32_t& r3, uint32_t a) {
    asm volatile("ldmatrix.sync.aligned.m8n8.x4.trans.shared.b16 {%0,%1,%2,%3}, [%4];"
                 : "=r"(r0), "=r"(r1), "=r"(r2), "=r"(r3) : "r"(a));
}
__device__ __forceinline__ void mma_f16(float* c, const uint32_t* a,
                                        uint32_t b0, uint32_t b1) {
    asm volatile(
        "mma.sync.aligned.m16n8k16.row.col.f32.f16.f16.f32 "
        "{%0,%1,%2,%3}, {%4,%5,%6,%7}, {%8,%9}, {%0,%1,%2,%3};"
        : "+f"(c[0]), "+f"(c[1]), "+f"(c[2]), "+f"(c[3])
        : "r"(a[0]), "r"(a[1]), "r"(a[2]), "r"(a[3]), "r"(b0), "r"(b1));
}
__device__ __forceinline__ uint32_t h2u(__half2 v) {
    union { __half2 h; uint32_t u; } cv; cv.h = v; return cv.u;
}
__device__ __forceinline__ void store_split(__half* Ch, __half* Cl,
                                            size_t off, float v0, float v1) {
    __half h0 = __float2half(v0), h1 = __float2half(v1);
    *(__half2*)(Ch + off) = __halves2half2(h0, h1);
    *(__half2*)(Cl + off) = __halves2half2(
        __float2half(v0 - __half2float(h0)),
        __float2half(v1 - __half2float(h1)));
}

// ==================== conversion kernels ===================================
// plain fp32 -> fp16 convert (x)
__global__ void conv_vec(const float* __restrict__ src,
                         __half* __restrict__ h, int n4) {
    int i = blockIdx.x * blockDim.x + threadIdx.x;
    int stride = gridDim.x * blockDim.x;
    __half2* H = (__half2*)h;
    for (; i < n4; i += stride) {
        float4 v = ((const float4*)src)[i];
        H[2*i]     = __halves2half2(__float2half(v.x), __float2half(v.y));
        H[2*i + 1] = __halves2half2(__float2half(v.z), __float2half(v.w));
    }
}

// fused transpose (hi only) for Wq|Wk|Wv -> g_Wth rows [0,2304)
__global__ void tsplit_qkv(const float* __restrict__ Wq,
                           const float* __restrict__ Wk,
                           const float* __restrict__ Wv,
                           __half* __restrict__ dh) {
    __shared__ float t[32][33];
    const float* src; int N, n0, rowOff;
    int nb = blockIdx.x;
    if (nb < 64)      { src = Wq; N = 2048; n0 = nb * 32;        rowOff = 0; }
    else if (nb < 68) { src = Wk; N = 128;  n0 = (nb - 64) * 32; rowOff = 2048; }
    else              { src = Wv; N = 128;  n0 = (nb - 68) * 32; rowOff = 2176; }
    int k0 = blockIdx.y * 32;
    int tx = threadIdx.x, ty = threadIdx.y;     // 32 x 8
    #pragma unroll
    for (int r = 0; r < 4; r++)
        t[ty + r*8][tx] = src[(size_t)(k0 + ty + r*8) * N + n0 + tx];
    __syncthreads();
    #pragma unroll
    for (int r = 0; r < 4; r++) {
        int n = n0 + ty + r*8, k = k0 + tx;
        dh[(size_t)(n + rowOff) * GK + k] = __float2half(t[tx][ty + r*8]);
    }
}

// transpose (hi only) for Wo
__global__ void tsplit(const float* __restrict__ src,
                       __half* __restrict__ dh, int N) {
    __shared__ float t[32][33];
    int n0 = blockIdx.x * 32, k0 = blockIdx.y * 32;
    int tx = threadIdx.x, ty = threadIdx.y;
    #pragma unroll
    for (int r = 0; r < 4; r++)
        t[ty + r*8][tx] = src[(size_t)(k0 + ty + r*8) * N + n0 + tx];
    __syncthreads();
    #pragma unroll
    for (int r = 0; r < 4; r++) {
        int n = n0 + ty + r*8, k = k0 + tx;
        dh[(size_t)n * GK + k] = __float2half(t[tx][ty + r*8]);
    }
}

// ==================== mma.sync 1-term fp16 GEMM ============================
// C = Ah*Bh (error ~4e-4 RMS relative).
// CTA 128x128, 8 warps (2 in M x 4 in N), warp tile 64x32, K-chunk 32,
// 3-stage cp.async (CP_WAIT(1), prefetch-before-compute), 2 CTAs/SM.
#define KC      32
#define LDSE    40
#define ROW2    (LDSE*2)                 // 80 B
// stage rows: [0,128) A-hi | [128,256) B-hi
#define BH_OFF  (128*ROW2)
#define STAGE_B (256*ROW2)               // 20480 B
#define NSTG    3
#define GSMEM   (NSTG*STAGE_B)           // 61440 B
#define NCHUNK  (GK/KC)                  // 64

__global__ __launch_bounds__(256, 2)
void gemm_mma(const __half* __restrict__ Ah, const __half* __restrict__ Bh,
              __half* __restrict__ Ch, __half* __restrict__ Cl,
              float* __restrict__ Cf, const float* __restrict__ bias, int ldc) {
    extern __shared__ char smem[];
    const uint32_t sb = smem_u32(smem);

    const int tid  = threadIdx.x;
    const int wid  = tid >> 5;
    const int lane = tid & 31;
    const int wm   = wid >> 2;
    const int wn   = wid & 3;
    const int row0 = blockIdx.y * 128;
    const int n0   = blockIdx.x * 128;

    const __half* pAh = Ah + (size_t)row0 * GK;
    const __half* pBh = Bh + (size_t)n0 * GK;

    float acc[4][4][4];
    #pragma unroll
    for (int i = 0; i < 4; i++)
        #pragma unroll
        for (int j = 0; j < 4; j++) {
            acc[i][j][0] = 0.f; acc[i][j][1] = 0.f;
            acc[i][j][2] = 0.f; acc[i][j][3] = 0.f;
        }

    const int a_row = wm * 64 + (lane & 15);
    const int a_col = (lane >> 4) * 8;
    const int b_g   = lane >> 3;
    const int b_row = wn * 32 + ((b_g >> 1) * 8) + (lane & 7);
    const int b_col = (b_g & 1) * 8;

    // cp.async: 1024 16B chunks per stage, 4 per thread
    auto load_stage = [&](int s, int c) {
        const uint32_t st = sb + s * STAGE_B;
        const int k0 = c * KC;
        #pragma unroll
        for (int it = 0; it < 4; ++it) {
            int f = tid + it * 256;          // 0..1023
            int r = f >> 2;                  // smem row 0..255
            int c16 = f & 3;
            uint32_t so = (uint32_t)(r * ROW2 + c16 * 16);
            const __half* src;
            if (r < 128) src = pAh + (size_t)r * GK + k0 + c16 * 8;
            else         src = pBh + (size_t)(r - 128) * GK + k0 + c16 * 8;
            cp_async16(st + so, src);
        }
        CP_COMMIT();
    };

    load_stage(0, 0);
    load_stage(1, 1);

    int s = 0;                               // stage of chunk c
    for (int c = 0; c < NCHUNK; ++c) {
        CP_WAIT(1);
        __syncthreads();
        if (c + 2 < NCHUNK) {
            int s2 = s + 2; if (s2 >= NSTG) s2 -= NSTG;
            load_stage(s2, c + 2);           // stage (c-1)%3: freed by the barrier
        }

        const uint32_t st = sb + s * STAGE_B;

        #pragma unroll
        for (int ks = 0; ks < 2; ++ks) {
            uint32_t bh[8];
            #pragma unroll
            for (int nb = 0; nb < 2; ++nb) {
                uint32_t off = (uint32_t)((b_row + nb*16) * ROW2
                                          + (b_col + ks*16) * 2);
                ldm_x4(bh[nb*4+0], bh[nb*4+1], bh[nb*4+2], bh[nb*4+3],
                       st + BH_OFF + off);
            }
            #pragma unroll
            for (int mi = 0; mi < 4; ++mi) {
                uint32_t ah[4];
                uint32_t off = (uint32_t)((a_row + mi*16) * ROW2
                                          + (a_col + ks*16) * 2);
                ldm_x4(ah[0], ah[1], ah[2], ah[3], st + off);
                #pragma unroll
                for (int ni = 0; ni < 4; ++ni)
                    mma_f16(acc[mi][ni], ah, bh[ni*2], bh[ni*2+1]);
            }
        }
        if (++s == NSTG) s = 0;
    }

    const int er = lane >> 2;
    const int ec = (lane & 3) * 2;
    #pragma unroll
    for (int mi = 0; mi < 4; ++mi) {
        #pragma unroll
        for (int ni = 0; ni < 4; ++ni) {
            int gr = row0 + wm*64 + mi*16 + er;
            int gc = n0 + wn*32 + ni*8 + ec;
            if (Cf) {
                float bx = 0.f, by = 0.f;
                if (bias) { bx = bias[gc]; by = bias[gc + 1]; }
                float2 v0 = make_float2(acc[mi][ni][0] + bx, acc[mi][ni][1] + by);
                float2 v1 = make_float2(acc[mi][ni][2] + bx, acc[mi][ni][3] + by);
                *(float2*)&Cf[(size_t)gr * ldc + gc]       = v0;
                *(float2*)&Cf[(size_t)(gr + 8) * ldc + gc] = v1;
            } else {
                store_split(Ch, Cl, (size_t)gr * ldc + gc,
                            acc[mi][ni][0], acc[mi][ni][1]);
                store_split(Ch, Cl, (size_t)(gr + 8) * ldc + gc,
                            acc[mi][ni][2], acc[mi][ni][3]);
            }
        }
    }
}

// ==================== tensor-core causal MQA flash attention ===============
// Per CTA: (b, h, 256-row Q tile). 8 warps x 32 Q rows.
// S = (Qh+Ql)*Kh (2-term). PV = Ph*Vh (1-term).
// KV tiles of 32 keys (Kh|Vh), 3-stage pipeline. Output: fp16 hi only.
#define LDA     136
#define ROWB    (LDA*2)                  // 272 B
#define QL_OFF  (256*ROWB)
#define KV0     (512*ROWB)
#define AVH     (32*ROWB)                // Vh offset within stage
#define KVSTAGE (64*ROWB)
#define ATT_SMEM (KV0 + 3*KVSTAGE)       // 191488 B

__global__ __launch_bounds__(256, 1)
void attn_mma() {
    extern __shared__ char smc[];
    const uint32_t sb = smem_u32(smc);
    const int tid = threadIdx.x, w = tid >> 5, lane = tid & 31;
    const int qt = blockIdx.x, h = blockIdx.y, b = blockIdx.z;
    const int q0 = qt * 256;
    const size_t qrow = (size_t)(b * TLEN + q0);

    auto load_kv = [&](int jt, int s) {
        const size_t krow = (size_t)(b * TLEN + jt * 32);
        const uint32_t base = sb + KV0 + s * KVSTAGE;
        #pragma unroll
        for (int it = 0; it < 4; ++it) {
            int f = tid + it * 256;          // 0..1023
            int arr = f >> 9;                // 0 Kh, 1 Vh
            int r   = (f >> 4) & 31;
            int c   = f & 15;
            const __half* src = g_Ch + (krow + r) * NQKV
                                + (arr ? 2176 : 2048) + c * 8;
            cp_async16(base + arr * AVH + r * ROWB + c * 16, src);
        }
        CP_COMMIT();
    };

    // ---- prefetch Q tile (256 rows hi+lo) + first two KV tiles ----
    #pragma unroll
    for (int it = 0; it < 32; ++it) {
        int f = tid + it * 256;              // 0..8191
        int arr = f >> 12;                   // 0=hi 1=lo
        int r   = (f >> 4) & 255;
        int c   = f & 15;
        const __half* src = (arr ? g_Cl : g_Ch)
            + (qrow + r) * NQKV + h * DH + c * 8;
        cp_async16(sb + arr * QL_OFF + r * ROWB + c * 16, src);
    }
    load_kv(0, 0);   // commits Q + KV0 together
    load_kv(1, 1);

    const int bg = lane >> 3;
    const uint32_t qa = sb + (32*w + (lane & 15)) * ROWB + ((lane >> 4) * 8) * 2;
    const uint32_t koff = (((bg >> 1) * 8) + (lane & 7)) * ROWB + ((bg & 1) * 8) * 2;
    const uint32_t voff = (((bg & 1) * 8) + (lane & 7)) * ROWB + ((bg >> 1) * 8) * 2;

    float O[2][16][4];
    #pragma unroll
    for (int mi = 0; mi < 2; mi++)
        #pragma unroll
        for (int i = 0; i < 16; i++) {
            O[mi][i][0]=0.f; O[mi][i][1]=0.f; O[mi][i][2]=0.f; O[mi][i][3]=0.f;
        }
    float m[2][2], l[2][2];
    m[0][0]=m[0][1]=m[1][0]=m[1][1] = -1e30f;
    l[0][0]=l[0][1]=l[1][0]=l[1][1] = 0.f;
    const float scale = 0.08838834764831845f;   // 1/sqrt(128)

    const int ntile = 8 * qt + 8;
    int sst = 0;
    for (int jt = 0; jt < ntile; ++jt) {
        CP_WAIT(1);
        __syncthreads();
        if (jt + 2 < ntile) {
            int s2 = sst + 2; if (s2 >= 3) s2 -= 3;
            load_kv(jt + 2, s2);
        }
        const uint32_t st = sb + KV0 + sst * KVSTAGE;
        if (++sst == 3) sst = 0;

        if (jt * 32 > q0 + 32*w + 31) continue;   // fully masked for this warp

        const uint32_t ka = st + koff;
        const uint32_t va = st + AVH + voff;

        // ---- S = Q K^T (2-term: (Qh+Ql)*Kh) ----
        float S[2][4][4];
        #pragma unroll
        for (int mi = 0; mi < 2; mi++)
            #pragma unroll
            for (int i = 0; i < 4; i++) {
                S[mi][i][0]=0.f; S[mi][i][1]=0.f; S[mi][i][2]=0.f; S[mi][i][3]=0.f;
            }

        #pragma unroll
        for (int ks = 0; ks < 8; ++ks) {
            uint32_t ah[2][4], al[2][4];
            #pragma unroll
            for (int mi = 0; mi < 2; ++mi) {
                ldm_x4(ah[mi][0], ah[mi][1], ah[mi][2], ah[mi][3],
                       qa + mi*(16*ROWB) + ks*32);
                ldm_x4(al[mi][0], al[mi][1], al[mi][2], al[mi][3],
                       qa + QL_OFF + mi*(16*ROWB) + ks*32);
            }
            #pragma unroll
            for (int nn = 0; nn < 2; ++nn) {
                uint32_t kh[4];
                ldm_x4(kh[0], kh[1], kh[2], kh[3],
                       ka + nn*(16*ROWB) + ks*32);
                #pragma unroll
                for (int mi = 0; mi < 2; ++mi) {
                    mma_f16(S[mi][2*nn],   ah[mi], kh[0], kh[1]);
                    mma_f16(S[mi][2*nn],   al[mi], kh[0], kh[1]);
                    mma_f16(S[mi][2*nn+1], ah[mi], kh[2], kh[3]);
                    mma_f16(S[mi][2*nn+1], al[mi], kh[2], kh[3]);
                }
            }
        }

        // ---- scale + causal mask + online softmax ----
        const bool edge = (jt * 32 + 31 > q0 + 32*w);
        const int cb = jt*32 + 2*(lane & 3);
        uint32_t phi[2][2][4];
        #pragma unroll
        for (int mi = 0; mi < 2; ++mi) {
            const int gr0 = q0 + 32*w + 16*mi + (lane >> 2);
            #pragma unroll
            for (int nt = 0; nt < 4; ++nt) {
                S[mi][nt][0] *= scale; S[mi][nt][1] *= scale;
                S[mi][nt][2] *= scale; S[mi][nt][3] *= scale;
            }
            if (edge) {
                #pragma unroll
                for (int nt = 0; nt < 4; ++nt) {
                    int gk = cb + 8*nt;
                    if (gk     > gr0)     S[mi][nt][0] = -1e30f;
                    if (gk + 1 > gr0)     S[mi][nt][1] = -1e30f;
                    if (gk     > gr0 + 8) S[mi][nt][2] = -1e30f;
                    if (gk + 1 > gr0 + 8) S[mi][nt][3] = -1e30f;
                }
            }

            float rm0 = -1e30f, rm1 = -1e30f;
            #pragma unroll
            for (int nt = 0; nt < 4; ++nt) {
                rm0 = fmaxf(rm0, fmaxf(S[mi][nt][0], S[mi][nt][1]));
                rm1 = fmaxf(rm1, fmaxf(S[mi][nt][2], S[mi][nt][3]));
            }
            rm0 = fmaxf(rm0, __shfl_xor_sync(0xffffffffu, rm0, 1));
            rm0 = fmaxf(rm0, __shfl_xor_sync(0xffffffffu, rm0, 2));
            rm1 = fmaxf(rm1, __shfl_xor_sync(0xffffffffu, rm1, 1));
            rm1 = fmaxf(rm1, __shfl_xor_sync(0xffffffffu, rm1, 2));
            float mn0 = fmaxf(m[mi][0], rm0), mn1 = fmaxf(m[mi][1], rm1);
            float a0 = __expf(m[mi][0] - mn0), a1 = __expf(m[mi][1] - mn1);
            m[mi][0] = mn0; m[mi][1] = mn1;

            float rs0 = 0.f, rs1 = 0.f;
            #pragma unroll
            for (int nt = 0; nt < 4; ++nt) {
                float p0 = __expf(S[mi][nt][0] - mn0), p1 = __expf(S[mi][nt][1] - mn0);
                float p2 = __expf(S[mi][nt][2] - mn1), p3 = __expf(S[mi][nt][3] - mn1);
                rs0 += p0 + p1;  rs1 += p2 + p3;
                int ki = nt >> 1, sl = (nt & 1) * 2;
                phi[mi][ki][sl+0] = h2u(__halves2half2(__float2half(p0),
                                                       __float2half(p1)));
                phi[mi][ki][sl+1] = h2u(__halves2half2(__float2half(p2),
                                                       __float2half(p3)));
            }
            rs0 += __shfl_xor_sync(0xffffffffu, rs0, 1);
            rs0 += __shfl_xor_sync(0xffffffffu, rs0, 2);
            rs1 += __shfl_xor_sync(0xffffffffu, rs1, 1);
            rs1 += __shfl_xor_sync(0xffffffffu, rs1, 2);
            l[mi][0] = l[mi][0] * a0 + rs0;
            l[mi][1] = l[mi][1] * a1 + rs1;

            #pragma unroll
            for (int ni = 0; ni < 16; ++ni) {
                O[mi][ni][0] *= a0; O[mi][ni][1] *= a0;
                O[mi][ni][2] *= a1; O[mi][ni][3] *= a1;
            }
        }

        // ---- O += Ph Vh (1-term) ----
        #pragma unroll
        for (int ki = 0; ki < 2; ++ki) {
            #pragma unroll
            for (int nb = 0; nb < 8; ++nb) {
                uint32_t vh[4];
                ldm_x4t(vh[0], vh[1], vh[2], vh[3],
                        va + ki*(16*ROWB) + nb*32);
                #pragma unroll
                for (int mi = 0; mi < 2; ++mi) {
                    mma_f16(O[mi][2*nb],   phi[mi][ki], vh[0], vh[1]);
                    mma_f16(O[mi][2*nb+1], phi[mi][ki], vh[2], vh[3]);
                }
            }
        }
    }

    // ---- epilogue: normalize, convert to fp16, store (hi only) ----
    #pragma unroll
    for (int mi = 0; mi < 2; ++mi) {
        float il0 = 1.0f / l[mi][0], il1 = 1.0f / l[mi][1];
        size_t r0 = qrow + 32*w + 16*mi + (lane >> 2);
        int colb = h * DH + 2 * (lane & 3);
        #pragma unroll
        for (int ni = 0; ni < 16; ++ni) {
            int col = colb + 8 * ni;
            *(__half2*)(g_Ah + r0 * EMB + col) = __halves2half2(
                __float2half(O[mi][ni][0] * il0),
                __float2half(O[mi][ni][1] * il0));
            *(__half2*)(g_Ah + (r0 + 8) * EMB + col) = __halves2half2(
                __float2half(O[mi][ni][2] * il1),
                __float2half(O[mi][ni][3] * il1));
        }
    }
}

// ==================== launch ===============================================
extern "C" void kernel_launch(void* const* d_in, const int* in_sizes, int n_in,
                              void* d_out, int out_size) {
    const float* x  = (const float*)d_in[0];
    const float* Wq = (const float*)d_in[1];
    const float* Wk = (const float*)d_in[2];
    const float* Wv = (const float*)d_in[3];
    const float* Wo = (const float*)d_in[4];
    const float* bo = (const float*)d_in[5];
    float* out = (float*)d_out;
    (void)in_sizes; (void)n_in; (void)out_size;

    void *pXh, *pAh, *pWth, *pWoth, *pCh, *pCl;
    cudaGetSymbolAddress(&pXh, g_Xh);
    cudaGetSymbolAddress(&pAh, g_Ah);
    cudaGetSymbolAddress(&pWth, g_Wth);   cudaGetSymbolAddress(&pWoth, g_Woth);
    cudaGetSymbolAddress(&pCh, g_Ch);     cudaGetSymbolAddress(&pCl, g_Cl);

    cudaFuncSetAttribute(gemm_mma, cudaFuncAttributeMaxDynamicSharedMemorySize, GSMEM);
    cudaFuncSetAttribute(attn_mma, cudaFuncAttributeMaxDynamicSharedMemorySize, ATT_SMEM);

    // 1) convert x to fp16; transpose weights (hi only)
    conv_vec<<<4096, 256>>>(x, (__half*)pXh, MROWS * EMB / 4);
    tsplit_qkv<<<dim3(72, 64), dim3(32, 8)>>>(Wq, Wk, Wv, (__half*)pWth);
    tsplit<<<dim3(64, 64), dim3(32, 8)>>>(Wo, (__half*)pWoth, 2048);

    // 2) fused QKV projection (1-term) -> split fp16 g_Ch/g_Cl
    gemm_mma<<<dim3(NQKV / 128, MROWS / 128), 256, GSMEM>>>(
        (const __half*)pXh, (const __half*)pWth,
        (__half*)pCh, (__half*)pCl, nullptr, nullptr, NQKV);

    // 3) tensor-core causal MQA flash attention -> fp16 g_Ah
    attn_mma<<<dim3(TLEN / 256, NH, BSZ), 256, ATT_SMEM>>>();

    // 4) O-projection (1-term) with fused bias -> fp32 out
    gemm_mma<<<dim3(EMB / 128, MROWS / 128), 256, GSMEM>>>(
        (const __half*)pAh, (const __half*)pWoth,
        nullptr, nullptr, out, bo, EMB);
}